// round 9
// baseline (speedup 1.0000x reference)
#include <cuda_runtime.h>
#include <cuda_bf16.h>
#include <cstdint>
#include <math.h>

#define B_  64
#define T_  1024
#define I_  512
#define H_  1024

// ===================== f32x2 helpers (proj kernel) ==========================
__device__ __forceinline__ unsigned long long f2fma(unsigned long long a,
                                                    unsigned long long b,
                                                    unsigned long long c) {
    unsigned long long d;
    asm("fma.rn.f32x2 %0, %1, %2, %3;" : "=l"(d) : "l"(a), "l"(b), "l"(c));
    return d;
}
__device__ __forceinline__ unsigned long long f2dup(float x) {
    unsigned long long d;
    asm("mov.b64 %0, {%1, %1};" : "=l"(d) : "f"(x));
    return d;
}
__device__ __forceinline__ float2 f2unpack(unsigned long long v) {
    float2 r;
    asm("mov.b64 {%0, %1}, %2;" : "=f"(r.x), "=f"(r.y) : "l"(v));
    return r;
}

// ===================== warp-mma / cluster helpers ===========================
__device__ __forceinline__ uint32_t smem_u32(const void* p) {
    uint32_t a;
    asm("{ .reg .u64 t; cvta.to.shared.u64 t, %1; cvt.u32.u64 %0, t; }"
        : "=r"(a) : "l"(p));
    return a;
}
__device__ __forceinline__ void ldsm4(uint32_t& r0, uint32_t& r1,
                                      uint32_t& r2, uint32_t& r3, uint32_t a) {
    asm volatile("ldmatrix.sync.aligned.m8n8.x4.shared.b16 {%0,%1,%2,%3}, [%4];"
                 : "=r"(r0), "=r"(r1), "=r"(r2), "=r"(r3) : "r"(a));
}
__device__ __forceinline__ void mma_bf16(float* c, const uint32_t* a,
                                         uint32_t b0, uint32_t b1) {
    asm volatile("mma.sync.aligned.m16n8k16.row.col.f32.bf16.bf16.f32 "
                 "{%0,%1,%2,%3}, {%4,%5,%6,%7}, {%8,%9}, {%0,%1,%2,%3};"
                 : "+f"(c[0]), "+f"(c[1]), "+f"(c[2]), "+f"(c[3])
                 : "r"(a[0]), "r"(a[1]), "r"(a[2]), "r"(a[3]),
                   "r"(b0), "r"(b1));
}
__device__ __forceinline__ uint32_t mapa_sh(uint32_t addr, uint32_t rank) {
    uint32_t r;
    asm("mapa.shared::cluster.u32 %0, %1, %2;" : "=r"(r) : "r"(addr), "r"(rank));
    return r;
}
__device__ __forceinline__ void st_clu_v2(uint32_t a, float x, float y) {
    asm volatile("st.shared::cluster.v2.f32 [%0], {%1,%2};"
                 :: "r"(a), "f"(x), "f"(y) : "memory");
}

// ===================== global scratch =======================================
// h state stored as the exact swizzled bf16 SMEM tile images:
// [buf][hi=0/lo=1][kg image 0..7][16384 bytes]
__device__ unsigned char g_hsp[2][2][8][16384];
__device__ unsigned g_flag[128];            // per-CTA step flags

__global__ void init_kernel() {
    int idx = blockIdx.x * blockDim.x + threadIdx.x;   // 16384 threads
    ((uint4*)g_hsp[0])[idx] = make_uint4(0, 0, 0, 0);  // zero buf 0 (h0 = 0)
    if (idx < 128) g_flag[idx] = 0u;
}

// ===================== Phase 1: xp = x @ input_w + b ========================
#define PTM 128
#define PTN 64
#define PTK 32
#define ASTR 132
#define BSTR 68

__global__ void __launch_bounds__(256)
proj_kernel(const float* __restrict__ x, const float* __restrict__ wi,
            const float* __restrict__ bias, float* __restrict__ out) {
    __shared__ float As[PTK * ASTR];
    __shared__ float Bs[PTK * BSTR];
    const int tid = threadIdx.x;
    const int m0 = blockIdx.y * PTM;
    const int n0 = blockIdx.x * PTN;
    const int ty = tid >> 4;
    const int tx = tid & 15;

    unsigned long long acc[8][2];
#pragma unroll
    for (int i = 0; i < 8; ++i) { acc[i][0] = 0ull; acc[i][1] = 0ull; }

    for (int kt = 0; kt < I_ / PTK; ++kt) {
        const int k0 = kt * PTK;
#pragma unroll
        for (int i = 0; i < 4; ++i) {
            int idx = tid + i * 256;
            int row = idx >> 3;
            int kl  = (idx & 7) << 2;
            float4 v = *(const float4*)(x + (size_t)(m0 + row) * I_ + k0 + kl);
            As[(kl + 0) * ASTR + row] = v.x;
            As[(kl + 1) * ASTR + row] = v.y;
            As[(kl + 2) * ASTR + row] = v.z;
            As[(kl + 3) * ASTR + row] = v.w;
        }
#pragma unroll
        for (int i = 0; i < 2; ++i) {
            int idx = tid + i * 256;
            int kr  = idx >> 4;
            int c4  = (idx & 15) << 2;
            float4 v = *(const float4*)(wi + (size_t)(k0 + kr) * H_ + n0 + c4);
            *(float4*)&Bs[kr * BSTR + c4] = v;
        }
        __syncthreads();
#pragma unroll
        for (int k = 0; k < PTK; ++k) {
            float a[8];
            *(float4*)&a[0] = *(const float4*)&As[k * ASTR + ty * 8];
            *(float4*)&a[4] = *(const float4*)&As[k * ASTR + ty * 8 + 4];
            ulonglong2 bv = *(const ulonglong2*)&Bs[k * BSTR + tx * 4];
#pragma unroll
            for (int i = 0; i < 8; ++i) {
                unsigned long long ad = f2dup(a[i]);
                acc[i][0] = f2fma(ad, bv.x, acc[i][0]);
                acc[i][1] = f2fma(ad, bv.y, acc[i][1]);
            }
        }
        __syncthreads();
    }
    float4 bb = *(const float4*)(bias + n0 + tx * 4);
#pragma unroll
    for (int i = 0; i < 8; ++i) {
        float2 lo = f2unpack(acc[i][0]);
        float2 hi = f2unpack(acc[i][1]);
        float4 o;
        o.x = lo.x + bb.x; o.y = lo.y + bb.y;
        o.z = hi.x + bb.z; o.w = hi.y + bb.w;
        *(float4*)(out + (size_t)(m0 + ty * 8 + i) * H_ + n0 + tx * 4) = o;
    }
}

// ===================== Phase 2: clustered HMMA recurrence ===================
// 128 CTAs = 16 clusters of 8: cluster = the 8 k-groups of one n-group.
// CTA(kg,ng): M=64 x N=64 x K=128 split-bf16 HMMA; partial reduction via
// DSMEM scatter + barrier.cluster; ONE global flag barrier per step.
#define A_HI 0
#define A_LO 16384
#define W_HI 32768
#define W_LO 49152
#define RED_OFF 65536                      // [8 src][8 rows][64 cols] fp32 = 16 KB
#define RNN_SMEM_BYTES 81920

__device__ __forceinline__ uint32_t tswz(int row, int k) {
    uint32_t kb = (uint32_t)(k * 2);
    return (uint32_t)(row * 256) + ((((kb >> 4) ^ (row & 7)) << 4) | (kb & 15));
}

__global__ void __launch_bounds__(256, 1) __cluster_dims__(8, 1, 1)
rnn_mma_kernel(const float* __restrict__ W, float* __restrict__ out) {
    extern __shared__ char smem[];
    const uint32_t sb = smem_u32(smem);
    const int tid  = threadIdx.x;
    const int wid  = tid >> 5;
    const int lane = tid & 31;
    const int kg   = blockIdx.x & 7;     // cluster rank
    const int ng   = blockIdx.x >> 3;    // 0..15
    const int ksl  = kg * 128;
    const int nsl  = ng * 64;

    // ---- build W^T hi/lo tiles once: Wt[n][k] = W[ksl+k][nsl+n] ----
    for (int q = tid; q < 64 * 128; q += 256) {
        int k = q >> 6;
        int n = q & 63;
        float w = W[(size_t)(ksl + k) * H_ + nsl + n];
        __nv_bfloat16 hi = __float2bfloat16_rn(w);
        __nv_bfloat16 lo = __float2bfloat16_rn(w - __bfloat162float(hi));
        uint32_t off = tswz(n, k);
        *(unsigned short*)(smem + W_HI + off) = *(unsigned short*)&hi;
        *(unsigned short*)(smem + W_LO + off) = *(unsigned short*)&lo;
    }
    __syncthreads();

    const int m0  = (wid & 3) * 16;
    const int n0w = (wid >> 2) * 32;
    const int lr  = lane & 15;
    const int kh  = lane >> 4;

    const uint32_t a_row_hi = sb + A_HI + (uint32_t)((m0 + lr) * 256);
    const uint32_t a_row_lo = sb + A_LO + (uint32_t)((m0 + lr) * 256);
    const uint32_t w_row0_h = sb + W_HI + (uint32_t)((n0w + lr) * 256);
    const uint32_t w_row1_h = sb + W_HI + (uint32_t)((n0w + 16 + lr) * 256);
    const uint32_t w_row0_l = sb + W_LO + (uint32_t)((n0w + lr) * 256);
    const uint32_t w_row1_l = sb + W_LO + (uint32_t)((n0w + 16 + lr) * 256);
    const uint32_t swz_a = (uint32_t)(lane & 7);

    // ---- DSMEM scatter targets (row -> owning CTA rank = row>>3) ----
    const int ra_ = m0 + (lane >> 2);
    const int rb_ = ra_ + 8;
    const int colb = n0w + 2 * (lane & 3);
    const uint32_t offA = mapa_sh(sb + RED_OFF, (uint32_t)(ra_ >> 3))
                        + (uint32_t)((kg * 512 + (ra_ & 7) * 64 + colb) * 4);
    const uint32_t offB = mapa_sh(sb + RED_OFF, (uint32_t)(rb_ >> 3))
                        + (uint32_t)((kg * 512 + (rb_ & 7) * 64 + colb) * 4);

    // ---- reducer assignment: 2 output elems (float2) per thread ----
    const int e   = tid * 2;
    const int rr  = e >> 6;              // 0..7
    const int cc  = e & 63;
    const int eb  = kg * 8 + rr;         // global row
    const int kg2 = ng >> 1;             // h image holding our cols
    const int kimg = (ng & 1) * 64 + cc;
    const uint32_t hoff = tswz(eb, kimg);

    for (int t = 0; t < T_; ++t) {
        // ---- global flag barrier: all CTAs finished step t-1 ----
        if (tid < 128) {
            unsigned v;
            const unsigned tgt = (unsigned)t;
            unsigned* fp = &g_flag[tid];
            do { asm volatile("ld.acquire.gpu.global.u32 %0, [%1];"
                              : "=r"(v) : "l"(fp)); } while (v < tgt);
        }
        __syncthreads();

        // ---- prefetch xp (independent) ----
        size_t obase = ((size_t)eb * T_ + t) * H_ + nsl + cc;
        float2 xv = __ldcg((const float2*)(out + obase));

        // ---- stage A hi/lo images (raw 16KB copies; already swizzled) ----
        const uint4* srcH = (const uint4*)(g_hsp[t & 1][0][kg]);
        const uint4* srcL = (const uint4*)(g_hsp[t & 1][1][kg]);
#pragma unroll
        for (int i = 0; i < 4; ++i) {
            uint4 vh = __ldcg(srcH + i * 256 + tid);
            uint4 vl = __ldcg(srcL + i * 256 + tid);
            *(uint4*)(smem + A_HI + i * 4096 + tid * 16) = vh;
            *(uint4*)(smem + A_LO + i * 4096 + tid * 16) = vl;
        }
        __syncthreads();

        // ---- mma mainloop: K=128, 8 k16-steps, 3 split products ----
        float c[4][4];
#pragma unroll
        for (int j = 0; j < 4; ++j)
            c[j][0] = c[j][1] = c[j][2] = c[j][3] = 0.f;

#pragma unroll
        for (int s = 0; s < 8; ++s) {
            const uint32_t ca  = (uint32_t)(((2 * s + kh) ^ swz_a) << 4);
            const uint32_t cw0 = (uint32_t)(((2 * s + kh) ^ (lr & 7)) << 4);
            uint32_t ah[4], al[4];
            uint32_t x0, x1, x2, x3;
            ldsm4(ah[0], ah[1], ah[2], ah[3], a_row_hi + ca);
            ldsm4(al[0], al[1], al[2], al[3], a_row_lo + ca);
            ldsm4(x0, x1, x2, x3, w_row0_h + cw0);
            uint32_t bh0 = x0, bh1 = x2, bh0b = x1, bh1b = x3;
            ldsm4(x0, x1, x2, x3, w_row1_h + cw0);
            uint32_t bh2 = x0, bh3 = x2, bh2b = x1, bh3b = x3;
            ldsm4(x0, x1, x2, x3, w_row0_l + cw0);
            uint32_t bl0 = x0, bl1 = x2, bl0b = x1, bl1b = x3;
            ldsm4(x0, x1, x2, x3, w_row1_l + cw0);
            uint32_t bl2 = x0, bl3 = x2, bl2b = x1, bl3b = x3;

            mma_bf16(c[0], ah, bh0, bh1);
            mma_bf16(c[1], ah, bh0b, bh1b);
            mma_bf16(c[2], ah, bh2, bh3);
            mma_bf16(c[3], ah, bh2b, bh3b);
            mma_bf16(c[0], ah, bl0, bl1);
            mma_bf16(c[1], ah, bl0b, bl1b);
            mma_bf16(c[2], ah, bl2, bl3);
            mma_bf16(c[3], ah, bl2b, bl3b);
            mma_bf16(c[0], al, bh0, bh1);
            mma_bf16(c[1], al, bh0b, bh1b);
            mma_bf16(c[2], al, bh2, bh3);
            mma_bf16(c[3], al, bh2b, bh3b);
        }

        // ---- scatter partials to owning CTAs via DSMEM ----
#pragma unroll
        for (int j = 0; j < 4; ++j) {
            st_clu_v2(offA + j * 32, c[j][0], c[j][1]);
            st_clu_v2(offB + j * 32, c[j][2], c[j][3]);
        }
        asm volatile("barrier.cluster.arrive.aligned;" ::: "memory");
        asm volatile("barrier.cluster.wait.aligned;" ::: "memory");

        // ---- reduce 8 sources, add xp, tanh, write out + split h ----
        {
            float2 s2 = make_float2(0.f, 0.f);
#pragma unroll
            for (int s8 = 0; s8 < 8; ++s8) {
                float2 pv = *(const float2*)(smem + RED_OFF
                                             + (s8 * 512 + rr * 64 + cc) * 4);
                s2.x += pv.x; s2.y += pv.y;
            }
            float2 hn;
            hn.x = tanhf(s2.x + xv.x);
            hn.y = tanhf(s2.y + xv.y);
            __stcg((float2*)(out + obase), hn);

            __nv_bfloat16 hx = __float2bfloat16_rn(hn.x);
            __nv_bfloat16 hy = __float2bfloat16_rn(hn.y);
            __nv_bfloat16 lx = __float2bfloat16_rn(hn.x - __bfloat162float(hx));
            __nv_bfloat16 ly = __float2bfloat16_rn(hn.y - __bfloat162float(hy));
            __nv_bfloat162 hp; hp.x = hx; hp.y = hy;
            __nv_bfloat162 lp; lp.x = lx; lp.y = ly;
            const int nb = (t + 1) & 1;
            __stcg((unsigned int*)(g_hsp[nb][0][kg2] + hoff), *(unsigned int*)&hp);
            __stcg((unsigned int*)(g_hsp[nb][1][kg2] + hoff), *(unsigned int*)&lp);
        }

        // ---- arrive: this CTA finished step t ----
        __syncthreads();
        if (tid == 0)
            asm volatile("st.release.gpu.global.u32 [%0], %1;"
                         :: "l"(&g_flag[blockIdx.x]), "r"((unsigned)(t + 1))
                         : "memory");
    }
}

// ===================== launch ===============================================
extern "C" void kernel_launch(void* const* d_in, const int* in_sizes, int n_in,
                              void* d_out, int out_size) {
    const float *x = nullptr, *hw = nullptr, *iw = nullptr, *bias = nullptr;
    for (int i = 0; i < n_in; ++i) {
        long long s = in_sizes[i];
        if      (s == (long long)B_ * T_ * I_) x    = (const float*)d_in[i];
        else if (s == (long long)H_ * H_)      hw   = (const float*)d_in[i];
        else if (s == (long long)I_ * H_)      iw   = (const float*)d_in[i];
        else if (s == (long long)H_)           bias = (const float*)d_in[i];
    }
    float* out = (float*)d_out;

    cudaFuncSetAttribute(rnn_mma_kernel,
                         cudaFuncAttributeMaxDynamicSharedMemorySize,
                         RNN_SMEM_BYTES);

    dim3 pgrid(H_ / PTN, (B_ * T_) / PTM);   // (16, 512)
    proj_kernel<<<pgrid, 256>>>(x, iw, bias, out);
    init_kernel<<<64, 256>>>();
    rnn_mma_kernel<<<128, 256, RNN_SMEM_BYTES>>>(hw, out);
}

// round 10
// speedup vs baseline: 1.4794x; 1.4794x over previous
#include <cuda_runtime.h>
#include <cuda_bf16.h>
#include <cstdint>
#include <math.h>

#define B_  64
#define T_  1024
#define I_  512
#define H_  1024

// ===================== f32x2 helpers (proj kernel) ==========================
__device__ __forceinline__ unsigned long long f2fma(unsigned long long a,
                                                    unsigned long long b,
                                                    unsigned long long c) {
    unsigned long long d;
    asm("fma.rn.f32x2 %0, %1, %2, %3;" : "=l"(d) : "l"(a), "l"(b), "l"(c));
    return d;
}
__device__ __forceinline__ unsigned long long f2dup(float x) {
    unsigned long long d;
    asm("mov.b64 %0, {%1, %1};" : "=l"(d) : "f"(x));
    return d;
}
__device__ __forceinline__ float2 f2unpack(unsigned long long v) {
    float2 r;
    asm("mov.b64 {%0, %1}, %2;" : "=f"(r.x), "=f"(r.y) : "l"(v));
    return r;
}

// ===================== warp-mma helpers =====================================
__device__ __forceinline__ uint32_t smem_u32(const void* p) {
    uint32_t a;
    asm("{ .reg .u64 t; cvta.to.shared.u64 t, %1; cvt.u32.u64 %0, t; }"
        : "=r"(a) : "l"(p));
    return a;
}
__device__ __forceinline__ void ldsm4(uint32_t& r0, uint32_t& r1,
                                      uint32_t& r2, uint32_t& r3, uint32_t a) {
    asm volatile("ldmatrix.sync.aligned.m8n8.x4.shared.b16 {%0,%1,%2,%3}, [%4];"
                 : "=r"(r0), "=r"(r1), "=r"(r2), "=r"(r3) : "r"(a));
}
__device__ __forceinline__ void mma_bf16(float* c, const uint32_t* a,
                                         uint32_t b0, uint32_t b1) {
    asm volatile("mma.sync.aligned.m16n8k16.row.col.f32.bf16.bf16.f32 "
                 "{%0,%1,%2,%3}, {%4,%5,%6,%7}, {%8,%9}, {%0,%1,%2,%3};"
                 : "+f"(c[0]), "+f"(c[1]), "+f"(c[2]), "+f"(c[3])
                 : "r"(a[0]), "r"(a[1]), "r"(a[2]), "r"(a[3]),
                   "r"(b0), "r"(b1));
}
__device__ __forceinline__ void poll_ge(unsigned* p, unsigned tgt) {
    unsigned v;
    do { asm volatile("ld.acquire.gpu.global.u32 %0, [%1];"
                      : "=r"(v) : "l"(p)); } while (v < tgt);
}
__device__ __forceinline__ void rel_add1(unsigned* p) {
    asm volatile("red.release.gpu.global.add.u32 [%0], 1;" :: "l"(p) : "memory");
}

// ===================== global scratch =======================================
// h state as pre-swizzled bf16 tile images: [buf][hi/lo][kg image][16384 B]
__device__ unsigned char g_hsp[2][2][8][16384];
__device__ float    g_part[2][8][B_ * H_];  // K-group partials, double-buffered
__device__ unsigned g_prod[16];             // per-ng h-produced counters
__device__ unsigned g_rdone[8];             // per-kg h-staged counters
__device__ unsigned g_bar2[16];             // per-ng partial-ready counters

__global__ void init_kernel() {
    int idx = blockIdx.x * blockDim.x + threadIdx.x;   // 16384 threads
    ((uint4*)g_hsp[0])[idx] = make_uint4(0, 0, 0, 0);  // zero buf 0 (h0 = 0)
    if (idx < 16) { g_prod[idx] = 0u; g_bar2[idx] = 0u; }
    if (idx < 8)  g_rdone[idx] = 0u;
}

// ===================== Phase 1: xp = x @ input_w + b ========================
#define PTM 128
#define PTN 64
#define PTK 32
#define ASTR 132
#define BSTR 68

__global__ void __launch_bounds__(256)
proj_kernel(const float* __restrict__ x, const float* __restrict__ wi,
            const float* __restrict__ bias, float* __restrict__ out) {
    __shared__ float As[PTK * ASTR];
    __shared__ float Bs[PTK * BSTR];
    const int tid = threadIdx.x;
    const int m0 = blockIdx.y * PTM;
    const int n0 = blockIdx.x * PTN;
    const int ty = tid >> 4;
    const int tx = tid & 15;

    unsigned long long acc[8][2];
#pragma unroll
    for (int i = 0; i < 8; ++i) { acc[i][0] = 0ull; acc[i][1] = 0ull; }

    for (int kt = 0; kt < I_ / PTK; ++kt) {
        const int k0 = kt * PTK;
#pragma unroll
        for (int i = 0; i < 4; ++i) {
            int idx = tid + i * 256;
            int row = idx >> 3;
            int kl  = (idx & 7) << 2;
            float4 v = *(const float4*)(x + (size_t)(m0 + row) * I_ + k0 + kl);
            As[(kl + 0) * ASTR + row] = v.x;
            As[(kl + 1) * ASTR + row] = v.y;
            As[(kl + 2) * ASTR + row] = v.z;
            As[(kl + 3) * ASTR + row] = v.w;
        }
#pragma unroll
        for (int i = 0; i < 2; ++i) {
            int idx = tid + i * 256;
            int kr  = idx >> 4;
            int c4  = (idx & 15) << 2;
            float4 v = *(const float4*)(wi + (size_t)(k0 + kr) * H_ + n0 + c4);
            *(float4*)&Bs[kr * BSTR + c4] = v;
        }
        __syncthreads();
#pragma unroll
        for (int k = 0; k < PTK; ++k) {
            float a[8];
            *(float4*)&a[0] = *(const float4*)&As[k * ASTR + ty * 8];
            *(float4*)&a[4] = *(const float4*)&As[k * ASTR + ty * 8 + 4];
            ulonglong2 bv = *(const ulonglong2*)&Bs[k * BSTR + tx * 4];
#pragma unroll
            for (int i = 0; i < 8; ++i) {
                unsigned long long ad = f2dup(a[i]);
                acc[i][0] = f2fma(ad, bv.x, acc[i][0]);
                acc[i][1] = f2fma(ad, bv.y, acc[i][1]);
            }
        }
        __syncthreads();
    }
    float4 bb = *(const float4*)(bias + n0 + tx * 4);
#pragma unroll
    for (int i = 0; i < 8; ++i) {
        float2 lo = f2unpack(acc[i][0]);
        float2 hi = f2unpack(acc[i][1]);
        float4 o;
        o.x = lo.x + bb.x; o.y = lo.y + bb.y;
        o.z = hi.x + bb.z; o.w = hi.y + bb.w;
        *(float4*)(out + (size_t)(m0 + ty * 8 + i) * H_ + n0 + tx * 4) = o;
    }
}

// ===================== Phase 2: HMMA recurrence, cone-sync ==================
// 128 CTAs = 8 k-groups x 16 n-groups (no clusters). CTA: M=64 x N=64 x K=128
// split-bf16 HMMA. All sync via small monotonic cone counters (8/16 arrivals),
// non-critical waits hoisted to step top and polled by 4 parallel threads.
#define A_HI 0
#define A_LO 16384
#define W_HI 32768
#define W_LO 49152
#define RNN_SMEM_BYTES 65536

__device__ __forceinline__ uint32_t tswz(int row, int k) {
    uint32_t kb = (uint32_t)(k * 2);
    return (uint32_t)(row * 256) + ((((kb >> 4) ^ (row & 7)) << 4) | (kb & 15));
}

__global__ void __launch_bounds__(256, 1)
rnn_mma_kernel(const float* __restrict__ W, float* __restrict__ out) {
    extern __shared__ char smem[];
    const uint32_t sb = smem_u32(smem);
    const int tid  = threadIdx.x;
    const int wid  = tid >> 5;
    const int lane = tid & 31;
    const int kg   = blockIdx.x >> 4;    // 0..7
    const int ng   = blockIdx.x & 15;    // 0..15
    const int ksl  = kg * 128;
    const int nsl  = ng * 64;

    // ---- build W^T hi/lo tiles once: Wt[n][k] = W[ksl+k][nsl+n] ----
    for (int q = tid; q < 64 * 128; q += 256) {
        int k = q >> 6;
        int n = q & 63;
        float w = W[(size_t)(ksl + k) * H_ + nsl + n];
        __nv_bfloat16 hi = __float2bfloat16_rn(w);
        __nv_bfloat16 lo = __float2bfloat16_rn(w - __bfloat162float(hi));
        uint32_t off = tswz(n, k);
        *(unsigned short*)(smem + W_HI + off) = *(unsigned short*)&hi;
        *(unsigned short*)(smem + W_LO + off) = *(unsigned short*)&lo;
    }
    __syncthreads();

    const int m0  = (wid & 3) * 16;
    const int n0w = (wid >> 2) * 32;
    const int lr  = lane & 15;
    const int kh  = lane >> 4;

    const uint32_t a_row_hi = sb + A_HI + (uint32_t)((m0 + lr) * 256);
    const uint32_t a_row_lo = sb + A_LO + (uint32_t)((m0 + lr) * 256);
    const uint32_t w_row0_h = sb + W_HI + (uint32_t)((n0w + lr) * 256);
    const uint32_t w_row1_h = sb + W_HI + (uint32_t)((n0w + 16 + lr) * 256);
    const uint32_t w_row0_l = sb + W_LO + (uint32_t)((n0w + lr) * 256);
    const uint32_t w_row1_l = sb + W_LO + (uint32_t)((n0w + 16 + lr) * 256);
    const uint32_t swz_a = (uint32_t)(lane & 7);

    // partial-store mapping (CTA-local row = global batch row, M=64=B)
    const int ra_ = m0 + (lane >> 2);
    const int rb_ = ra_ + 8;
    const int colb = n0w + 2 * (lane & 3);

    // reducer / h-writer assignment: 2 output elems (float2) per thread
    const int e    = tid * 2;
    const int rr   = e >> 6;             // 0..7
    const int cc   = e & 63;
    const int eb   = kg * 8 + rr;        // global row this thread owns
    const int kg2  = ng >> 1;            // h image holding our columns
    const int kimg = (ng & 1) * 64 + cc;
    const uint32_t hoff = tswz(eb, kimg);

    for (int t = 0; t < T_; ++t) {
        // ---- top waits: 4 distinct counters polled by 4 parallel warps ----
        if (tid == 0) {
            poll_ge(&g_prod[2 * kg], 8u * (unsigned)t);          // h cols lo half
        } else if (tid == 32) {
            poll_ge(&g_prod[2 * kg + 1], 8u * (unsigned)t);      // h cols hi half
        } else if (tid == 64) {
            if (t >= 2) poll_ge(&g_prod[ng], 8u * (unsigned)(t - 1)); // g_part WAR
        } else if (tid == 96) {
            if (t >= 1) poll_ge(&g_rdone[kg2], 16u * (unsigned)t);    // h-image WAR
        }
        __syncthreads();

        // ---- prefetch xp (independent) ----
        size_t obase = ((size_t)eb * T_ + t) * H_ + nsl + cc;
        float2 xv = __ldcg((const float2*)(out + obase));

        // ---- stage A hi/lo images (raw 16KB copies; already swizzled) ----
        const uint4* srcH = (const uint4*)(g_hsp[t & 1][0][kg]);
        const uint4* srcL = (const uint4*)(g_hsp[t & 1][1][kg]);
#pragma unroll
        for (int i = 0; i < 4; ++i) {
            uint4 vh = __ldcg(srcH + i * 256 + tid);
            uint4 vl = __ldcg(srcL + i * 256 + tid);
            *(uint4*)(smem + A_HI + i * 4096 + tid * 16) = vh;
            *(uint4*)(smem + A_LO + i * 4096 + tid * 16) = vl;
        }
        __syncthreads();
        if (tid == 0) rel_add1(&g_rdone[kg]);   // h buf read complete

        // ---- mma mainloop: K=128, 8 k16-steps, 3 split products ----
        float c[4][4];
#pragma unroll
        for (int j = 0; j < 4; ++j)
            c[j][0] = c[j][1] = c[j][2] = c[j][3] = 0.f;

#pragma unroll
        for (int s = 0; s < 8; ++s) {
            const uint32_t ca  = (uint32_t)(((2 * s + kh) ^ swz_a) << 4);
            const uint32_t cw0 = (uint32_t)(((2 * s + kh) ^ (lr & 7)) << 4);
            uint32_t ah[4], al[4];
            uint32_t x0, x1, x2, x3;
            ldsm4(ah[0], ah[1], ah[2], ah[3], a_row_hi + ca);
            ldsm4(al[0], al[1], al[2], al[3], a_row_lo + ca);
            ldsm4(x0, x1, x2, x3, w_row0_h + cw0);
            uint32_t bh0 = x0, bh1 = x2, bh0b = x1, bh1b = x3;
            ldsm4(x0, x1, x2, x3, w_row1_h + cw0);
            uint32_t bh2 = x0, bh3 = x2, bh2b = x1, bh3b = x3;
            ldsm4(x0, x1, x2, x3, w_row0_l + cw0);
            uint32_t bl0 = x0, bl1 = x2, bl0b = x1, bl1b = x3;
            ldsm4(x0, x1, x2, x3, w_row1_l + cw0);
            uint32_t bl2 = x0, bl3 = x2, bl2b = x1, bl3b = x3;

            mma_bf16(c[0], ah, bh0, bh1);
            mma_bf16(c[1], ah, bh0b, bh1b);
            mma_bf16(c[2], ah, bh2, bh3);
            mma_bf16(c[3], ah, bh2b, bh3b);
            mma_bf16(c[0], ah, bl0, bl1);
            mma_bf16(c[1], ah, bl0b, bl1b);
            mma_bf16(c[2], ah, bl2, bl3);
            mma_bf16(c[3], ah, bl2b, bl3b);
            mma_bf16(c[0], al, bh0, bh1);
            mma_bf16(c[1], al, bh0b, bh1b);
            mma_bf16(c[2], al, bh2, bh3);
            mma_bf16(c[3], al, bh2b, bh3b);
        }

        // ---- store partials to global (WAR cleared by tid64's top wait) ----
        {
            const int pr = t & 1;
            float* pa = &g_part[pr][kg][(size_t)ra_ * H_ + nsl + colb];
            float* pb = &g_part[pr][kg][(size_t)rb_ * H_ + nsl + colb];
#pragma unroll
            for (int j = 0; j < 4; ++j) {
                __stcg((float2*)(pa + j * 8), make_float2(c[j][0], c[j][1]));
                __stcg((float2*)(pb + j * 8), make_float2(c[j][2], c[j][3]));
            }
        }
        __syncthreads();
        if (tid == 0) {
            rel_add1(&g_bar2[ng]);
            poll_ge(&g_bar2[ng], 8u * (unsigned)(t + 1));  // all 8 kg partials in
        }
        __syncthreads();

        // ---- reduce 8 partials, add xp, tanh, write out + split-h image ----
        {
            const int pr = t & 1;
            float2 s2 = make_float2(0.f, 0.f);
#pragma unroll
            for (int k2 = 0; k2 < 8; ++k2) {
                float2 pv = __ldcg((const float2*)(&g_part[pr][k2][(size_t)eb * H_ + nsl + cc]));
                s2.x += pv.x; s2.y += pv.y;
            }
            float2 hn;
            hn.x = tanhf(s2.x + xv.x);
            hn.y = tanhf(s2.y + xv.y);
            __stcg((float2*)(out + obase), hn);

            __nv_bfloat16 hx = __float2bfloat16_rn(hn.x);
            __nv_bfloat16 hy = __float2bfloat16_rn(hn.y);
            __nv_bfloat16 lx = __float2bfloat16_rn(hn.x - __bfloat162float(hx));
            __nv_bfloat16 ly = __float2bfloat16_rn(hn.y - __bfloat162float(hy));
            __nv_bfloat162 hp; hp.x = hx; hp.y = hy;
            __nv_bfloat162 lp; lp.x = lx; lp.y = ly;
            const int nb = (t + 1) & 1;
            __stcg((unsigned int*)(g_hsp[nb][0][kg2] + hoff), *(unsigned int*)&hp);
            __stcg((unsigned int*)(g_hsp[nb][1][kg2] + hoff), *(unsigned int*)&lp);
        }
        __syncthreads();
        if (tid == 0) rel_add1(&g_prod[ng]);   // h for step t published
    }
}

// ===================== launch ===============================================
extern "C" void kernel_launch(void* const* d_in, const int* in_sizes, int n_in,
                              void* d_out, int out_size) {
    const float *x = nullptr, *hw = nullptr, *iw = nullptr, *bias = nullptr;
    for (int i = 0; i < n_in; ++i) {
        long long s = in_sizes[i];
        if      (s == (long long)B_ * T_ * I_) x    = (const float*)d_in[i];
        else if (s == (long long)H_ * H_)      hw   = (const float*)d_in[i];
        else if (s == (long long)I_ * H_)      iw   = (const float*)d_in[i];
        else if (s == (long long)H_)           bias = (const float*)d_in[i];
    }
    float* out = (float*)d_out;

    cudaFuncSetAttribute(rnn_mma_kernel,
                         cudaFuncAttributeMaxDynamicSharedMemorySize,
                         RNN_SMEM_BYTES);

    dim3 pgrid(H_ / PTN, (B_ * T_) / PTM);   // (16, 512)
    proj_kernel<<<pgrid, 256>>>(x, iw, bias, out);
    init_kernel<<<64, 256>>>();
    rnn_mma_kernel<<<128, 256, RNN_SMEM_BYTES>>>(hw, out);
}